// round 9
// baseline (speedup 1.0000x reference)
#include <cuda_runtime.h>
#include <cuda_bf16.h>
#include <math_constants.h>

// Cox partial-likelihood loss via chunked sort + suffix sums.
//   risk_sum[i] = sum_j exp(theta[j]) * (survtime[j] >= survtime[i])
//   loss = -mean((theta - log(risk_sum)) * censor)
//
// Kernel 1: split j into chunks of 512; each block bitonic-sorts its chunk by
//   time (carrying exp(theta) as payload) and builds an inclusive SUFFIX sum
//   of the payload. O(N log^2 C) total, deterministic (fixed network).
// Kernel 2: risk_sum[i] = sum over chunks of suffix[lower_bound(t_i)].
//   Binary search has a data-independent trip count (9 steps) -> no divergence.
//   Then contribution + block reduce + last-finisher writes the scalar.
//
// Exactness of the mask: lower_bound uses the same float '<' the reference's
// '>=' mask complements; ties sit adjacent after sorting, so suffix from the
// first equal time includes every t_j >= t_i. Only the FP summation order
// differs (well within 1e-3).
//
// Deterministic (fixed sort network, fixed-order scans/reductions, finisher
// sums in fixed index order). Graph-capturable: 2 launches, no allocs.

#define MAX_N        8192
#define CHUNK        512
#define MAX_CHUNKS   (MAX_N / CHUNK)        // 16
#define SORT_THREADS 256                    // CHUNK / 2 elems per thread = 2
#define LOSS_THREADS 1024
#define MAX_LB       ((MAX_N + LOSS_THREADS - 1) / LOSS_THREADS)  // 8

// Allocation-free scratch.
__device__ float g_stime[MAX_CHUNKS * CHUNK];   // sorted times per chunk
__device__ float g_ssuf[MAX_CHUNKS * CHUNK];    // per-chunk suffix sums of exp
__device__ float g_bsum[MAX_LB];
__device__ unsigned g_done = 0;

// ---------------------------------------------------------------------------
// Kernel 1: per-chunk bitonic sort (ascending by time) + suffix sums.
// ---------------------------------------------------------------------------
__global__ void __launch_bounds__(SORT_THREADS)
sort_kernel(const float* __restrict__ y_true,
            const float* __restrict__ theta,
            int N)
{
    __shared__ float st[CHUNK];   // times (sort key)
    __shared__ float se[CHUNK];   // exp(theta) (payload)

    const int base = blockIdx.x * CHUNK;

    // Load + pad: +inf time / 0 payload contributes nothing and sorts last.
    for (int i = threadIdx.x; i < CHUNK; i += SORT_THREADS) {
        int j = base + i;
        if (j < N) { st[i] = y_true[2 * j]; se[i] = __expf(theta[j]); }
        else       { st[i] = CUDART_INF_F;  se[i] = 0.0f; }
    }
    __syncthreads();

    // Bitonic sort, ascending. Pairs within a stage are disjoint -> race-free.
    for (int k = 2; k <= CHUNK; k <<= 1) {
        for (int j = k >> 1; j > 0; j >>= 1) {
            for (int i = threadIdx.x; i < CHUNK; i += SORT_THREADS) {
                int ix = i ^ j;
                if (ix > i) {
                    float a = st[i], b = st[ix];
                    bool up = ((i & k) == 0);
                    if ((a > b) == up) {
                        st[i] = b; st[ix] = a;
                        float ea = se[i], eb = se[ix];
                        se[i] = eb; se[ix] = ea;
                    }
                }
            }
            __syncthreads();
        }
    }

    // Inclusive suffix sum of se (Hillis-Steele, register double-buffer).
    // CHUNK == 2 * SORT_THREADS exactly.
    for (int off = 1; off < CHUNK; off <<= 1) {
        int i0 = threadIdx.x, i1 = threadIdx.x + SORT_THREADS;
        float v0 = se[i0] + ((i0 + off < CHUNK) ? se[i0 + off] : 0.0f);
        float v1 = se[i1] + ((i1 + off < CHUNK) ? se[i1 + off] : 0.0f);
        __syncthreads();
        se[i0] = v0; se[i1] = v1;
        __syncthreads();
    }

    for (int i = threadIdx.x; i < CHUNK; i += SORT_THREADS) {
        g_stime[base + i] = st[i];
        g_ssuf[base + i]  = se[i];
    }
}

// ---------------------------------------------------------------------------
// Kernel 2: binary-search risk sums + loss.  Dynamic smem holds all chunks:
//   [ s_time : nchunks*CHUNK ][ s_suf : nchunks*CHUNK ]
// ---------------------------------------------------------------------------
extern __shared__ float dyn_smem[];

__global__ void __launch_bounds__(LOSS_THREADS)
loss_kernel(const float* __restrict__ y_true,
            const float* __restrict__ theta,
            float* __restrict__ out,
            int N, int nchunks, int lb)
{
    float* s_time = dyn_smem;
    float* s_suf  = dyn_smem + nchunks * CHUNK;
    __shared__ float red[LOSS_THREADS];

    const int M = nchunks * CHUNK;
    for (int i = threadIdx.x; i < M; i += LOSS_THREADS) {
        s_time[i] = g_stime[i];
        s_suf[i]  = g_ssuf[i];
    }
    __syncthreads();

    const int i = blockIdx.x * LOSS_THREADS + threadIdx.x;
    float contrib = 0.0f;
    if (i < N) {
        const float t = y_true[2 * i];
        float risk = 0.0f;
        for (int c = 0; c < nchunks; ++c) {
            const float* ts = s_time + c * CHUNK;
            // lower_bound: first idx with ts[idx] >= t. Interval halves from
            // CHUNK deterministically -> all lanes run exactly 9 iterations.
            int lo = 0, hi = CHUNK;
            while (lo < hi) {
                int mid = (lo + hi) >> 1;
                if (ts[mid] < t) lo = mid + 1; else hi = mid;
            }
            if (lo < CHUNK) risk += s_suf[c * CHUNK + lo];
        }
        float censor = (y_true[2 * i + 1] != 0.0f) ? 1.0f : 0.0f;
        contrib = (theta[i] - __logf(risk)) * censor;   // risk >= exp(theta_i) > 0
    }

    // Block reduction (fixed order).
    red[threadIdx.x] = contrib;
    __syncthreads();
    #pragma unroll
    for (int s = LOSS_THREADS / 2; s >= 32; s >>= 1) {
        if (threadIdx.x < s) red[threadIdx.x] += red[threadIdx.x + s];
        __syncthreads();
    }
    if (threadIdx.x < 32) {
        float v = red[threadIdx.x];
        #pragma unroll
        for (int o = 16; o > 0; o >>= 1)
            v += __shfl_down_sync(0xFFFFFFFFu, v, o);
        if (threadIdx.x == 0) {
            g_bsum[blockIdx.x] = v;
            __threadfence();
            unsigned fin = atomicAdd(&g_done, 1u);
            if (fin == (unsigned)lb - 1u) {       // last finisher
                g_done = 0;                        // reset for next replay
                __threadfence();
                float s = 0.0f;
                for (int b = 0; b < lb; ++b)       // fixed order -> deterministic
                    s += g_bsum[b];
                out[0] = -s / (float)N;
            }
        }
    }
}

// ---------------------------------------------------------------------------
extern "C" void kernel_launch(void* const* d_in, const int* in_sizes, int n_in,
                              void* d_out, int out_size)
{
    // Identify inputs by size: y_true has 2N elements, hazard_pred has N.
    const float* y_true;
    const float* theta;
    int N;
    if (in_sizes[0] == 2 * in_sizes[1]) {
        y_true = (const float*)d_in[0];
        theta  = (const float*)d_in[1];
        N = in_sizes[1];
    } else {
        theta  = (const float*)d_in[0];
        y_true = (const float*)d_in[1];
        N = in_sizes[0];
    }

    float* out = (float*)d_out;

    const int nchunks = (N + CHUNK - 1) / CHUNK;                 // 16
    const int lb      = (N + LOSS_THREADS - 1) / LOSS_THREADS;   // 8
    const size_t smem = (size_t)nchunks * CHUNK * 2 * sizeof(float);  // 64 KB

    // Opt-in for >48KB dynamic smem (not a stream op; capture-safe).
    cudaFuncSetAttribute(loss_kernel,
                         cudaFuncAttributeMaxDynamicSharedMemorySize,
                         (int)smem);

    sort_kernel<<<nchunks, SORT_THREADS>>>(y_true, theta, N);
    loss_kernel<<<lb, LOSS_THREADS, smem>>>(y_true, theta, out, N, nchunks, lb);
}

// round 10
// speedup vs baseline: 1.4227x; 1.4227x over previous
#include <cuda_runtime.h>
#include <cuda_bf16.h>
#include <math_constants.h>

// Cox partial-likelihood loss via chunked sort + suffix sums.
//   risk_sum[i] = sum_j exp(theta[j]) * (survtime[j] >= survtime[i])
//   loss = -mean((theta - log(risk_sum)) * censor)
//
// Kernel 1: split j into 16 chunks of 512; each block bitonic-sorts its chunk
//   by time (payload exp(theta)) and builds an inclusive suffix sum.
// Kernel 2: risk_sum[i] = sum over chunks of suffix[lower_bound(t_i)].
//   All 16 binary searches per thread are INTERLEAVED (lo/hi register arrays,
//   one step of every chunk per round) -> 16 independent LDS in flight per
//   round instead of a serial 29-cycle chain. 32 blocks x 256 threads.
//
// Mask exactness: lower_bound uses the same float '<' that complements the
// reference's '>='; ties are adjacent after sorting so the suffix includes
// every t_j >= t_i. Only FP summation order differs (<< 1e-3).
//
// Deterministic (fixed sort network, fixed-order scans/reductions, finisher
// sums in fixed index order). Graph-capturable: 2 launches, no allocs.

#define MAX_N        8192
#define CHUNK        512
#define LOG_CHUNK    9
#define NCH          16                     // fixed chunk slots (padded)
#define SORT_THREADS 256
#define LOSS_THREADS 256
#define MAX_LB       64

// Allocation-free scratch.
__device__ float g_stime[NCH * CHUNK];      // sorted times per chunk
__device__ float g_ssuf[NCH * CHUNK];       // per-chunk suffix sums of exp
__device__ float g_bsum[MAX_LB];
__device__ unsigned g_done = 0;

// ---------------------------------------------------------------------------
// Kernel 1: per-chunk bitonic sort (ascending by time) + suffix sum.
// ---------------------------------------------------------------------------
__global__ void __launch_bounds__(SORT_THREADS)
sort_kernel(const float* __restrict__ y_true,
            const float* __restrict__ theta,
            int N)
{
    __shared__ float st[CHUNK];   // times (key)
    __shared__ float se[CHUNK];   // exp(theta) (payload)

    const int base = blockIdx.x * CHUNK;

    // Load + pad: +inf time / 0 payload contributes nothing, sorts last.
    for (int i = threadIdx.x; i < CHUNK; i += SORT_THREADS) {
        int j = base + i;
        if (j < N) { st[i] = y_true[2 * j]; se[i] = __expf(theta[j]); }
        else       { st[i] = CUDART_INF_F;  se[i] = 0.0f; }
    }
    __syncthreads();

    // Bitonic sort, ascending. Disjoint pairs per stage -> race-free.
    for (int k = 2; k <= CHUNK; k <<= 1) {
        for (int j = k >> 1; j > 0; j >>= 1) {
            for (int i = threadIdx.x; i < CHUNK; i += SORT_THREADS) {
                int ix = i ^ j;
                if (ix > i) {
                    float a = st[i], b = st[ix];
                    bool up = ((i & k) == 0);
                    if ((a > b) == up) {
                        st[i] = b; st[ix] = a;
                        float ea = se[i], eb = se[ix];
                        se[i] = eb; se[ix] = ea;
                    }
                }
            }
            __syncthreads();
        }
    }

    // Inclusive suffix sum (Hillis-Steele, register double-buffer).
    for (int off = 1; off < CHUNK; off <<= 1) {
        int i0 = threadIdx.x, i1 = threadIdx.x + SORT_THREADS;
        float v0 = se[i0] + ((i0 + off < CHUNK) ? se[i0 + off] : 0.0f);
        float v1 = se[i1] + ((i1 + off < CHUNK) ? se[i1 + off] : 0.0f);
        __syncthreads();
        se[i0] = v0; se[i1] = v1;
        __syncthreads();
    }

    for (int i = threadIdx.x; i < CHUNK; i += SORT_THREADS) {
        g_stime[base + i] = st[i];
        g_ssuf[base + i]  = se[i];
    }
}

// ---------------------------------------------------------------------------
// Kernel 2: interleaved binary searches + loss.
// Dynamic smem: [ s_time : NCH*CHUNK ][ s_suf : NCH*CHUNK ]  (64 KB)
// ---------------------------------------------------------------------------
extern __shared__ float dyn_smem[];

__global__ void __launch_bounds__(LOSS_THREADS)
loss_kernel(const float* __restrict__ y_true,
            const float* __restrict__ theta,
            float* __restrict__ out,
            int N, int nchunks, int lb)
{
    float* s_time = dyn_smem;
    float* s_suf  = dyn_smem + NCH * CHUNK;
    __shared__ float red[LOSS_THREADS];

    // Stage all chunks; pad unused slots so they contribute exactly 0.
    const int M = nchunks * CHUNK;
    for (int i = threadIdx.x; i < NCH * CHUNK; i += LOSS_THREADS) {
        if (i < M) { s_time[i] = g_stime[i]; s_suf[i] = g_ssuf[i]; }
        else       { s_time[i] = CUDART_INF_F; s_suf[i] = 0.0f; }
    }
    __syncthreads();

    const int i = blockIdx.x * LOSS_THREADS + threadIdx.x;
    float contrib = 0.0f;
    if (i < N) {
        const float t = y_true[2 * i];

        // 16 interleaved lower_bound searches: one step of every chunk per
        // round -> 16 independent LDS in flight, latency overlapped.
        int lo[NCH], hi[NCH];
        #pragma unroll
        for (int c = 0; c < NCH; ++c) { lo[c] = 0; hi[c] = CHUNK; }

        #pragma unroll
        for (int s = 0; s < LOG_CHUNK; ++s) {
            #pragma unroll
            for (int c = 0; c < NCH; ++c) {
                int mid = (lo[c] + hi[c]) >> 1;
                float v = s_time[(c << LOG_CHUNK) + mid];
                if (v < t) lo[c] = mid + 1; else hi[c] = mid;
            }
        }

        float risk = 0.0f;
        #pragma unroll
        for (int c = 0; c < NCH; ++c)
            if (lo[c] < CHUNK) risk += s_suf[(c << LOG_CHUNK) + lo[c]];

        float censor = (y_true[2 * i + 1] != 0.0f) ? 1.0f : 0.0f;
        contrib = (theta[i] - __logf(risk)) * censor;   // risk >= exp(theta_i) > 0
    }

    // Block reduction (fixed order).
    red[threadIdx.x] = contrib;
    __syncthreads();
    #pragma unroll
    for (int s = LOSS_THREADS / 2; s >= 32; s >>= 1) {
        if (threadIdx.x < s) red[threadIdx.x] += red[threadIdx.x + s];
        __syncthreads();
    }
    if (threadIdx.x < 32) {
        float v = red[threadIdx.x];
        #pragma unroll
        for (int o = 16; o > 0; o >>= 1)
            v += __shfl_down_sync(0xFFFFFFFFu, v, o);
        if (threadIdx.x == 0) {
            g_bsum[blockIdx.x] = v;
            __threadfence();
            unsigned fin = atomicAdd(&g_done, 1u);
            if (fin == (unsigned)lb - 1u) {       // last finisher
                g_done = 0;                        // reset for next replay
                __threadfence();
                float s = 0.0f;
                for (int b = 0; b < lb; ++b)       // fixed order
                    s += g_bsum[b];
                out[0] = -s / (float)N;
            }
        }
    }
}

// ---------------------------------------------------------------------------
extern "C" void kernel_launch(void* const* d_in, const int* in_sizes, int n_in,
                              void* d_out, int out_size)
{
    // Identify inputs by size: y_true has 2N elements, hazard_pred has N.
    const float* y_true;
    const float* theta;
    int N;
    if (in_sizes[0] == 2 * in_sizes[1]) {
        y_true = (const float*)d_in[0];
        theta  = (const float*)d_in[1];
        N = in_sizes[1];
    } else {
        theta  = (const float*)d_in[0];
        y_true = (const float*)d_in[1];
        N = in_sizes[0];
    }

    float* out = (float*)d_out;

    const int nchunks = (N + CHUNK - 1) / CHUNK;                  // 16
    int lb = (N + LOSS_THREADS - 1) / LOSS_THREADS;               // 32
    if (lb > MAX_LB) lb = MAX_LB;                                 // N<=8192: never
    const size_t smem = (size_t)NCH * CHUNK * 2 * sizeof(float);  // 64 KB

    // Opt-in for >48KB dynamic smem (host-side attr; capture-safe).
    cudaFuncSetAttribute(loss_kernel,
                         cudaFuncAttributeMaxDynamicSharedMemorySize,
                         (int)smem);

    sort_kernel<<<nchunks, SORT_THREADS>>>(y_true, theta, N);
    loss_kernel<<<lb, LOSS_THREADS, smem>>>(y_true, theta, out, N, nchunks, lb);
}

// round 14
// speedup vs baseline: 1.5333x; 1.0778x over previous
#include <cuda_runtime.h>
#include <cuda_bf16.h>
#include <math_constants.h>

// Cox partial-likelihood loss — ONE kernel, chunked sort + suffix sums.
//   risk_sum[i] = sum_j exp(theta[j]) * (survtime[j] >= survtime[i])
//   loss = -mean((theta - log(risk_sum)) * censor)
//
// 16 blocks x 512 threads. Block c:
//   Phase 1: bitonic-sort its 512-element chunk by time (payload exp(theta))
//            in OWN smem; inclusive suffix-sum the payload.
//   Phase 2: for ALL N i's (16 interleaved binary searches per thread) look
//            up suffix[lower_bound(t_i)] in its OWN smem table; write the
//            partial risk to g_part[c][i] (coalesced). No cross-block table
//            traffic at all.
//   -- one grid barrier (16 blocks, all co-resident: trivially safe) --
//   Phase 3: block b sums the 16 partials for its 512 i's, computes
//            (theta - log(risk)) * censor, block-reduces; last finisher sums
//            block results in fixed order and writes the scalar.
//
// Mask exactness: lower_bound uses the float '<' complementing the reference
// '>='; ties are adjacent after sorting, so the suffix covers all t_j >= t_i.
// Deterministic: fixed sort network, fixed-order scans/reductions, finisher
// sums in fixed index order. Graph-capturable: 1 launch, no allocs.

#define CHUNK     512
#define LOG_CHUNK 9
#define NCH       16
#define THREADS   512
#define MAX_N     (NCH * CHUNK)             // 8192
#define IG        (MAX_N / THREADS)         // 16 i-groups per thread

// Allocation-free scratch.
__device__ float g_part[NCH * MAX_N];       // partial risk per (chunk, i)
__device__ float g_bsum[NCH];
__device__ unsigned g_bar_count = 0;
__device__ unsigned g_bar_gen   = 0;
__device__ unsigned g_done      = 0;

__global__ void __launch_bounds__(THREADS)
cox_kernel(const float* __restrict__ y_true,
           const float* __restrict__ theta,
           float* __restrict__ out,
           int N)
{
    __shared__ float st[CHUNK];     // sorted times
    __shared__ float se[CHUNK];     // exp(theta) -> suffix sums
    __shared__ float red[THREADS];

    const int c   = blockIdx.x;
    const int tid = threadIdx.x;
    const int base = c * CHUNK;

    // ---- Phase 1a: load + pad (+inf key / 0 payload sorts last, adds 0) ---
    {
        int j = base + tid;
        if (j < N) { st[tid] = y_true[2 * j]; se[tid] = __expf(theta[j]); }
        else       { st[tid] = CUDART_INF_F;  se[tid] = 0.0f; }
    }
    __syncthreads();

    // ---- Phase 1b: bitonic sort ascending (1 elem/thread, fixed network) --
    for (int k = 2; k <= CHUNK; k <<= 1) {
        for (int j = k >> 1; j > 0; j >>= 1) {
            int ix = tid ^ j;
            if (ix > tid) {
                float a = st[tid], b = st[ix];
                bool up = ((tid & k) == 0);
                if ((a > b) == up) {
                    st[tid] = b; st[ix] = a;
                    float ea = se[tid], eb = se[ix];
                    se[tid] = eb; se[ix] = ea;
                }
            }
            __syncthreads();
        }
    }

    // ---- Phase 1c: inclusive suffix sum (Hillis-Steele) -------------------
    for (int off = 1; off < CHUNK; off <<= 1) {
        float v = se[tid] + ((tid + off < CHUNK) ? se[tid + off] : 0.0f);
        __syncthreads();
        se[tid] = v;
        __syncthreads();
    }

    // ---- Phase 2: search own table for ALL i (16 interleaved searches) ----
    float tq[IG];
    #pragma unroll
    for (int k = 0; k < IG; ++k) {
        int i = tid + k * THREADS;
        tq[k] = (i < N) ? y_true[2 * i] : 0.0f;
    }

    int lo[IG], hi[IG];
    #pragma unroll
    for (int k = 0; k < IG; ++k) { lo[k] = 0; hi[k] = CHUNK; }

    #pragma unroll
    for (int s = 0; s < LOG_CHUNK; ++s) {
        #pragma unroll
        for (int k = 0; k < IG; ++k) {
            int mid = (lo[k] + hi[k]) >> 1;
            float v = st[mid];
            if (v < tq[k]) lo[k] = mid + 1; else hi[k] = mid;
        }
    }

    #pragma unroll
    for (int k = 0; k < IG; ++k) {
        int i = tid + k * THREADS;
        if (i < N)
            g_part[c * MAX_N + i] = (lo[k] < CHUNK) ? se[lo[k]] : 0.0f;
    }

    // Publish partials, then grid barrier (16 blocks — all co-resident).
    __threadfence();
    __syncthreads();
    if (tid == 0) {
        volatile unsigned* genp = &g_bar_gen;
        unsigned gen = *genp;
        unsigned arrived = atomicAdd(&g_bar_count, 1u);
        if (arrived == gridDim.x - 1u) {
            g_bar_count = 0;
            __threadfence();
            atomicExch(&g_bar_gen, gen + 1u);       // release
        } else {
            while (*genp == gen) { __nanosleep(20); }
            __threadfence();                        // acquire
        }
    }
    __syncthreads();

    // ---- Phase 3: reduce partials + loss ----------------------------------
    const int i = c * THREADS + tid;        // 16*512 = 8192 >= N covered
    float contrib = 0.0f;
    if (i < N) {
        float risk = 0.0f;
        #pragma unroll
        for (int cc = 0; cc < NCH; ++cc)    // fixed order, coalesced
            risk += g_part[cc * MAX_N + i];
        float censor = (y_true[2 * i + 1] != 0.0f) ? 1.0f : 0.0f;
        contrib = (theta[i] - __logf(risk)) * censor;   // risk >= e^theta_i > 0
    }

    red[tid] = contrib;
    __syncthreads();
    #pragma unroll
    for (int s = THREADS / 2; s >= 32; s >>= 1) {
        if (tid < s) red[tid] += red[tid + s];
        __syncthreads();
    }
    if (tid < 32) {
        float v = red[tid];
        #pragma unroll
        for (int o = 16; o > 0; o >>= 1)
            v += __shfl_down_sync(0xFFFFFFFFu, v, o);
        if (tid == 0) {
            g_bsum[c] = v;
            __threadfence();
            unsigned fin = atomicAdd(&g_done, 1u);
            if (fin == gridDim.x - 1u) {            // last finisher
                g_done = 0;                          // reset for next replay
                __threadfence();
                float s = 0.0f;
                #pragma unroll
                for (int b = 0; b < NCH; ++b)        // fixed order
                    s += g_bsum[b];
                out[0] = -s / (float)N;
            }
        }
    }
}

// ---------------------------------------------------------------------------
extern "C" void kernel_launch(void* const* d_in, const int* in_sizes, int n_in,
                              void* d_out, int out_size)
{
    // Identify inputs by size: y_true has 2N elements, hazard_pred has N.
    const float* y_true;
    const float* theta;
    int N;
    if (in_sizes[0] == 2 * in_sizes[1]) {
        y_true = (const float*)d_in[0];
        theta  = (const float*)d_in[1];
        N = in_sizes[1];
    } else {
        theta  = (const float*)d_in[0];
        y_true = (const float*)d_in[1];
        N = in_sizes[0];
    }

    float* out = (float*)d_out;

    // Fixed 16-block grid (supports any N <= 8192; unused chunks self-pad).
    cox_kernel<<<NCH, THREADS>>>(y_true, theta, out, N);
}

// round 16
// speedup vs baseline: 2.0597x; 1.3433x over previous
#include <cuda_runtime.h>
#include <cuda_bf16.h>

// Cox partial-likelihood loss — brute-force O(N^2), tuned.
//   risk_sum[i] = sum_j exp(theta[j]) * (survtime[j] >= survtime[i])
//   loss = -mean((theta - log(risk_sum)) * censor)
//
// Kernel 1 (risk): 512 blocks (8 i-tiles x 64 j-tiles) x 256 threads.
//   j-chunk (time, exp(theta)) staged in smem; each thread owns 4 i's.
//   Inner loop per (i,j) pair is EXACTLY 2 instructions via inline-asm
//   predication: FSETP (alu pipe) + @p FADD (fma pipe). LDS.64 broadcast
//   amortized over 4 pairs -> 2.25 instr/pair, balanced across pipes.
// Kernel 2 (epilogue): 32 blocks x 256 threads; sums the 64 partials per i
//   (coalesced), computes (theta - log(risk)) * censor, block-reduces;
//   last-finishing block sums block results in fixed order -> scalar.
//
// Deterministic: fixed-slot partials, fixed-order reductions. Graph-
// capturable: 2 plain launches, no allocs, no sync APIs.

#define MAX_N       8192
#define J_TILES     64
#define JCHUNK_MAX  ((MAX_N + J_TILES - 1) / J_TILES)   // 128
#define THREADS     256
#define I_PER_THR   4
#define I_TILE      (THREADS * I_PER_THR)               // 1024
#define RED_THREADS 256
#define MAX_RB      64

// Allocation-free scratch.
__device__ float g_partial[J_TILES * MAX_N];            // 2 MB
__device__ float g_bsum[MAX_RB];
__device__ unsigned g_done = 0;

// ---------------------------------------------------------------------------
// Kernel 1: partial risk sums.
// ---------------------------------------------------------------------------
__global__ void __launch_bounds__(THREADS)
risk_kernel(const float* __restrict__ y_true,
            const float* __restrict__ theta,
            int N, int jchunk)
{
    __shared__ float2 sj[JCHUNK_MAX];

    const int itile = blockIdx.x;
    const int jt    = blockIdx.y;
    const int j0    = jt * jchunk;
    int jn = N - j0;
    if (jn > jchunk) jn = jchunk;
    if (jn < 0) jn = 0;

    // Stage (time, exp(theta)) for this j-chunk.
    for (int j = threadIdx.x; j < jn; j += THREADS) {
        float t = y_true[2 * (j0 + j)];
        float e = __expf(theta[j0 + j]);
        sj[j] = make_float2(t, e);
    }
    __syncthreads();

    const int ibase = itile * I_TILE + threadIdx.x;
    float ti[I_PER_THR];
    #pragma unroll
    for (int k = 0; k < I_PER_THR; ++k) {
        int i = ibase + k * THREADS;
        ti[k] = (i < N) ? y_true[2 * i] : 0.0f;
    }

    float acc[I_PER_THR];
    #pragma unroll
    for (int k = 0; k < I_PER_THR; ++k) acc[k] = 0.0f;

    #pragma unroll 8
    for (int j = 0; j < jn; ++j) {
        float2 v = sj[j];                       // LDS.64 broadcast
        #pragma unroll
        for (int k = 0; k < I_PER_THR; ++k) {
            // Exactly: FSETP.GE (alu) + @p FADD (fma). No select, no mul.
            asm volatile(
                "{ .reg .pred p;\n\t"
                "  setp.ge.f32 p, %1, %2;\n\t"
                "  @p add.f32 %0, %0, %3;\n\t"
                "}"
                : "+f"(acc[k])
                : "f"(v.x), "f"(ti[k]), "f"(v.y));
        }
    }

    #pragma unroll
    for (int k = 0; k < I_PER_THR; ++k) {
        int i = ibase + k * THREADS;
        if (i < N) g_partial[jt * N + i] = acc[k];
    }
}

// ---------------------------------------------------------------------------
// Kernel 2: fused contributions + final scalar (last-finisher).
// ---------------------------------------------------------------------------
__global__ void __launch_bounds__(RED_THREADS)
epilogue_kernel(const float* __restrict__ y_true,
                const float* __restrict__ theta,
                float* __restrict__ out,
                int N, int rb)
{
    __shared__ float red[RED_THREADS];

    const int i = blockIdx.x * RED_THREADS + threadIdx.x;
    float c = 0.0f;
    if (i < N) {
        float risk = 0.0f;
        #pragma unroll
        for (int jt = 0; jt < J_TILES; ++jt)    // fixed order, coalesced
            risk += g_partial[jt * N + i];
        float censor = (y_true[2 * i + 1] != 0.0f) ? 1.0f : 0.0f;
        c = (theta[i] - __logf(risk)) * censor; // risk >= exp(theta_i) > 0
    }

    red[threadIdx.x] = c;
    __syncthreads();
    #pragma unroll
    for (int s = RED_THREADS / 2; s >= 32; s >>= 1) {
        if (threadIdx.x < s) red[threadIdx.x] += red[threadIdx.x + s];
        __syncthreads();
    }
    if (threadIdx.x < 32) {
        float v = red[threadIdx.x];
        #pragma unroll
        for (int o = 16; o > 0; o >>= 1)
            v += __shfl_down_sync(0xFFFFFFFFu, v, o);
        if (threadIdx.x == 0) {
            g_bsum[blockIdx.x] = v;
            __threadfence();
            unsigned fin = atomicAdd(&g_done, 1u);
            if (fin == (unsigned)rb - 1u) {      // last finisher
                g_done = 0;                       // reset for next replay
                __threadfence();
                float s = 0.0f;
                for (int b = 0; b < rb; ++b)      // fixed order
                    s += g_bsum[b];
                out[0] = -s / (float)N;
            }
        }
    }
}

// ---------------------------------------------------------------------------
extern "C" void kernel_launch(void* const* d_in, const int* in_sizes, int n_in,
                              void* d_out, int out_size)
{
    // Identify inputs by size: y_true has 2N elements, hazard_pred has N.
    const float* y_true;
    const float* theta;
    int N;
    if (in_sizes[0] == 2 * in_sizes[1]) {
        y_true = (const float*)d_in[0];
        theta  = (const float*)d_in[1];
        N = in_sizes[1];
    } else {
        theta  = (const float*)d_in[0];
        y_true = (const float*)d_in[1];
        N = in_sizes[0];
    }

    float* out = (float*)d_out;

    const int jchunk = (N + J_TILES - 1) / J_TILES;      // 128 for N=8192
    const int itiles = (N + I_TILE - 1) / I_TILE;        // 8   for N=8192
    int rb = (N + RED_THREADS - 1) / RED_THREADS;        // 32  for N=8192
    if (rb > MAX_RB) rb = MAX_RB;                        // N<=16384 safe

    dim3 grid1(itiles, J_TILES);
    risk_kernel<<<grid1, THREADS>>>(y_true, theta, N, jchunk);
    epilogue_kernel<<<rb, RED_THREADS>>>(y_true, theta, out, N, rb);
}

// round 17
// speedup vs baseline: 2.0949x; 1.0171x over previous
#include <cuda_runtime.h>
#include <cuda_bf16.h>

// Cox partial-likelihood loss — brute-force O(N^2), tuned.
//   risk_sum[i] = sum_j exp(theta[j]) * (survtime[j] >= survtime[i])
//   loss = -mean((theta - log(risk_sum)) * censor)
//
// Kernel 1 (risk): 512 blocks (8 i-tiles x 64 j-tiles) x 256 threads.
//   j-chunk (time, exp(theta)) staged in smem; each thread owns 4 i's.
//   Inner loop per (i,j) pair: FSETP (alu) + @p FADD (fma) via inline asm
//   = exactly 2 instructions, LDS.64 broadcast amortized over 4 pairs.
// Kernel 2 (epilogue): 64 blocks x 256 threads. The two 128-thread halves
//   of a block each sum 32 of the 64 partials for the same 128 i's (8-wide
//   independent load batches -> high MLP), combine via smem, then
//   contribution + block reduce + fixed-order last-finisher scalar.
//
// Deterministic: fixed-slot partials, fixed-order reductions. Graph-
// capturable: 2 plain launches, no allocs, no sync APIs.

#define MAX_N       8192
#define J_TILES     64
#define JCHUNK_MAX  ((MAX_N + J_TILES - 1) / J_TILES)   // 128
#define THREADS     256
#define I_PER_THR   4
#define I_TILE      (THREADS * I_PER_THR)               // 1024
#define EPI_THREADS 256
#define EPI_IPB     128                                 // i's per epilogue block
#define MAX_RB      64

// Allocation-free scratch.
__device__ float g_partial[J_TILES * MAX_N];            // 2 MB
__device__ float g_bsum[MAX_RB];
__device__ unsigned g_done = 0;

// ---------------------------------------------------------------------------
// Kernel 1: partial risk sums.  (unchanged from the passing R16 version)
// ---------------------------------------------------------------------------
__global__ void __launch_bounds__(THREADS)
risk_kernel(const float* __restrict__ y_true,
            const float* __restrict__ theta,
            int N, int jchunk)
{
    __shared__ float2 sj[JCHUNK_MAX];

    const int itile = blockIdx.x;
    const int jt    = blockIdx.y;
    const int j0    = jt * jchunk;
    int jn = N - j0;
    if (jn > jchunk) jn = jchunk;
    if (jn < 0) jn = 0;

    for (int j = threadIdx.x; j < jn; j += THREADS) {
        float t = y_true[2 * (j0 + j)];
        float e = __expf(theta[j0 + j]);
        sj[j] = make_float2(t, e);
    }
    __syncthreads();

    const int ibase = itile * I_TILE + threadIdx.x;
    float ti[I_PER_THR];
    #pragma unroll
    for (int k = 0; k < I_PER_THR; ++k) {
        int i = ibase + k * THREADS;
        ti[k] = (i < N) ? y_true[2 * i] : 0.0f;
    }

    float acc[I_PER_THR];
    #pragma unroll
    for (int k = 0; k < I_PER_THR; ++k) acc[k] = 0.0f;

    #pragma unroll 8
    for (int j = 0; j < jn; ++j) {
        float2 v = sj[j];                       // LDS.64 broadcast
        #pragma unroll
        for (int k = 0; k < I_PER_THR; ++k) {
            // Exactly: FSETP.GE (alu) + @p FADD (fma).
            asm volatile(
                "{ .reg .pred p;\n\t"
                "  setp.ge.f32 p, %1, %2;\n\t"
                "  @p add.f32 %0, %0, %3;\n\t"
                "}"
                : "+f"(acc[k])
                : "f"(v.x), "f"(ti[k]), "f"(v.y));
        }
    }

    #pragma unroll
    for (int k = 0; k < I_PER_THR; ++k) {
        int i = ibase + k * THREADS;
        if (i < N) g_partial[jt * N + i] = acc[k];
    }
}

// ---------------------------------------------------------------------------
// Kernel 2: epilogue. 64 blocks x 256 threads; half-split over j-tiles.
// ---------------------------------------------------------------------------
__global__ void __launch_bounds__(EPI_THREADS)
epilogue_kernel(const float* __restrict__ y_true,
                const float* __restrict__ theta,
                float* __restrict__ out,
                int N, int rb)
{
    __shared__ float s_half[EPI_IPB];
    __shared__ float red[EPI_IPB];

    const int half = threadIdx.x >> 7;          // 0: jt 0..31, 1: jt 32..63
    const int li   = threadIdx.x & (EPI_IPB - 1);
    const int i    = blockIdx.x * EPI_IPB + li;

    // Sum 32 partials with 8 independent accumulators -> 8-deep load batches.
    float acc[8];
    #pragma unroll
    for (int a = 0; a < 8; ++a) acc[a] = 0.0f;

    if (i < N) {
        const int jt0 = half * 32;
        #pragma unroll
        for (int g = 0; g < 4; ++g) {
            #pragma unroll
            for (int a = 0; a < 8; ++a)         // 8 independent LDGs in flight
                acc[a] += g_partial[(jt0 + g * 8 + a) * N + i];
        }
    }
    // Fixed-order pairwise combine (deterministic).
    float sum = ((acc[0] + acc[1]) + (acc[2] + acc[3]))
              + ((acc[4] + acc[5]) + (acc[6] + acc[7]));

    if (half == 1) s_half[li] = sum;
    __syncthreads();

    float c = 0.0f;
    if (half == 0) {
        if (i < N) {
            float risk = sum + s_half[li];      // fixed order: low half + high
            float censor = (y_true[2 * i + 1] != 0.0f) ? 1.0f : 0.0f;
            c = (theta[i] - __logf(risk)) * censor;  // risk >= e^theta_i > 0
        }
        red[li] = c;
    }
    __syncthreads();

    // Reduce 128 contributions (tid < 128 only).
    if (threadIdx.x < 64) red[threadIdx.x] += red[threadIdx.x + 64];
    __syncthreads();
    if (threadIdx.x < 32) {
        float v = red[threadIdx.x] + red[threadIdx.x + 32];
        #pragma unroll
        for (int o = 16; o > 0; o >>= 1)
            v += __shfl_down_sync(0xFFFFFFFFu, v, o);
        if (threadIdx.x == 0) {
            g_bsum[blockIdx.x] = v;
            __threadfence();
            unsigned fin = atomicAdd(&g_done, 1u);
            if (fin == (unsigned)rb - 1u) {     // last finisher
                g_done = 0;                      // reset for next replay
                __threadfence();
                float s = 0.0f;
                for (int b = 0; b < rb; ++b)     // fixed order
                    s += g_bsum[b];
                out[0] = -s / (float)N;
            }
        }
    }
}

// ---------------------------------------------------------------------------
extern "C" void kernel_launch(void* const* d_in, const int* in_sizes, int n_in,
                              void* d_out, int out_size)
{
    // Identify inputs by size: y_true has 2N elements, hazard_pred has N.
    const float* y_true;
    const float* theta;
    int N;
    if (in_sizes[0] == 2 * in_sizes[1]) {
        y_true = (const float*)d_in[0];
        theta  = (const float*)d_in[1];
        N = in_sizes[1];
    } else {
        theta  = (const float*)d_in[0];
        y_true = (const float*)d_in[1];
        N = in_sizes[0];
    }

    float* out = (float*)d_out;

    const int jchunk = (N + J_TILES - 1) / J_TILES;      // 128 for N=8192
    const int itiles = (N + I_TILE - 1) / I_TILE;        // 8   for N=8192
    int rb = (N + EPI_IPB - 1) / EPI_IPB;                // 64  for N=8192
    if (rb > MAX_RB) rb = MAX_RB;                        // N<=8192 safe

    dim3 grid1(itiles, J_TILES);
    risk_kernel<<<grid1, THREADS>>>(y_true, theta, N, jchunk);
    epilogue_kernel<<<rb, EPI_THREADS>>>(y_true, theta, out, N, rb);
}